// round 3
// baseline (speedup 1.0000x reference)
#include <cuda_runtime.h>
#include <cuda_bf16.h>
#include <math.h>

// Problem constants
#define QM 8
#define VV 6890
#define KN 16
#define EE 256
#define HH 8
#define DD 32
#define NTOK (QM * VV)          // 55120
#define FF (4 * EE)             // 1024

// Scratch (static device globals; no runtime allocation)
__device__ float g_qkv[(size_t)NTOK * 768];   // [N][q|k|v]
__device__ float g_o[(size_t)NTOK * EE];      // attention output
__device__ float g_x[(size_t)NTOK * EE];      // post-LN1 x (residual for FFN)
__device__ float g_h[(size_t)NTOK * FF];      // GELU(FFN1)

// Canonicalized index/mask buffers + dtype flags
__device__ int g_idx64;                       // 1 if indices are int64
__device__ int g_mask32;                      // 1 if mask is int32
__device__ int g_cidx[(size_t)NTOK * KN];     // b*V + g as int32
__device__ unsigned char g_cmask[(size_t)NTOK * KN];

// ---------------------------------------------------------------------------
// Dtype detection (deterministic; sample-based with ~0 misdetection prob)
// ---------------------------------------------------------------------------
__global__ void detect_kernel(const void* bidx, const void* mask)
{
    __shared__ int s_is64, s_m32;
    if (threadIdx.x == 0) { s_is64 = 1; s_m32 = 1; }
    __syncthreads();

    // Indices: bidx values are in [0, 8). If data is int32, the int64 view of
    // a pair = lo + hi*2^32 with hi nonzero w.p. 7/8 -> huge values appear.
    // If truly int64, every value < 8.
    const unsigned long long* b64 = (const unsigned long long*)bidx;
    for (int i = threadIdx.x; i < 1024; i += blockDim.x)
        if (b64[i] >= (1ull << 32)) atomicExch(&s_is64, 0);

    // Mask: if packed bool bytes, a uint32 view combines 4 bools -> values > 1
    // appear w.p. ~0.657 per group. If int32 {0,1}, all values <= 1.
    const unsigned int* m32 = (const unsigned int*)mask;
    for (int i = threadIdx.x; i < 1024; i += blockDim.x)
        if (m32[i] > 1u) atomicExch(&s_m32, 0);

    __syncthreads();
    if (threadIdx.x == 0) { g_idx64 = s_is64; g_mask32 = s_m32; }
}

__global__ void convert_kernel(const void* bidx, const void* graph, const void* mask)
{
    const int is64 = g_idx64;
    const int m32  = g_mask32;
    const int total = NTOK * KN;
    for (int i = blockIdx.x * blockDim.x + threadIdx.x; i < total;
         i += gridDim.x * blockDim.x) {
        int b, g;
        if (is64) {
            b = (int)((const long long*)bidx)[i];
            g = (int)((const long long*)graph)[i];
        } else {
            b = ((const int*)bidx)[i];
            g = ((const int*)graph)[i];
        }
        g_cidx[i] = b * VV + g;
        g_cmask[i] = m32 ? (unsigned char)(((const int*)mask)[i] != 0)
                         : ((const unsigned char*)mask)[i];
    }
}

// ---------------------------------------------------------------------------
// GEMM: C[M, Ncols] = A[M, Kd] @ W[Ncols, Kd]^T + bias (+ res) (GELU optional)
// BM=BN=128, BK=16, TM=TN=8, 256 threads.
// ---------------------------------------------------------------------------
__device__ __forceinline__ float gelu_exact(float x) {
    return 0.5f * x * (1.0f + erff(x * 0.7071067811865475f));
}

template<bool HASRES, bool DOGELU>
__global__ void __launch_bounds__(256)
gemm_kernel(const float* __restrict__ A, const float* __restrict__ W,
            const float* __restrict__ bias, float* __restrict__ C,
            const float* __restrict__ res,
            int M, int Kd, int ldc)
{
    __shared__ float As[16][132];
    __shared__ float Bs[16][132];

    const int tid = threadIdx.x;
    const int tx = tid & 15;
    const int ty = tid >> 4;
    const int row0 = blockIdx.x * 128;
    const int col0 = blockIdx.y * 128;

    float acc[8][8];
#pragma unroll
    for (int i = 0; i < 8; i++)
#pragma unroll
        for (int j = 0; j < 8; j++) acc[i][j] = 0.0f;

    const int lm  = tid >> 2;        // 0..63
    const int lk4 = (tid & 3) * 4;   // 0,4,8,12

    for (int kb = 0; kb < Kd; kb += 16) {
#pragma unroll
        for (int half = 0; half < 2; half++) {
            const int m = lm + half * 64;
            const int r = row0 + m;
            float4 av = make_float4(0.f, 0.f, 0.f, 0.f);
            if (r < M)
                av = *(const float4*)(A + (size_t)r * Kd + kb + lk4);
            As[lk4 + 0][m] = av.x;
            As[lk4 + 1][m] = av.y;
            As[lk4 + 2][m] = av.z;
            As[lk4 + 3][m] = av.w;

            const int nn = lm + half * 64;
            float4 bv = *(const float4*)(W + (size_t)(col0 + nn) * Kd + kb + lk4);
            Bs[lk4 + 0][nn] = bv.x;
            Bs[lk4 + 1][nn] = bv.y;
            Bs[lk4 + 2][nn] = bv.z;
            Bs[lk4 + 3][nn] = bv.w;
        }
        __syncthreads();

#pragma unroll
        for (int k = 0; k < 16; k++) {
            float a[8], b[8];
            *(float4*)(a)     = *(const float4*)&As[k][ty * 8];
            *(float4*)(a + 4) = *(const float4*)&As[k][ty * 8 + 4];
            *(float4*)(b)     = *(const float4*)&Bs[k][tx * 8];
            *(float4*)(b + 4) = *(const float4*)&Bs[k][tx * 8 + 4];
#pragma unroll
            for (int i = 0; i < 8; i++)
#pragma unroll
                for (int j = 0; j < 8; j++)
                    acc[i][j] = fmaf(a[i], b[j], acc[i][j]);
        }
        __syncthreads();
    }

#pragma unroll
    for (int i = 0; i < 8; i++) {
        const int r = row0 + ty * 8 + i;
        if (r >= M) continue;
#pragma unroll
        for (int j = 0; j < 8; j++) {
            const int cg = col0 + tx * 8 + j;
            float v = acc[i][j] + bias[cg];
            if (HASRES) v += res[(size_t)r * ldc + cg];
            if (DOGELU) v = gelu_exact(v);
            C[(size_t)r * ldc + cg] = v;
        }
    }
}

// ---------------------------------------------------------------------------
// Attention: one block per token n (256 threads = 8 warps = 8 heads).
// Lane = head-dim element (D=32). Scores via butterfly reduce; softmax over 16.
// ---------------------------------------------------------------------------
__global__ void __launch_bounds__(256)
attn_kernel(const float* __restrict__ qkv, float* __restrict__ o)
{
    const int n = blockIdx.x;
    __shared__ int s_m[KN];
    __shared__ unsigned char s_mask[KN];

    const int tid = threadIdx.x;
    if (tid < KN) {
        s_m[tid] = g_cidx[(size_t)n * KN + tid];
        s_mask[tid] = g_cmask[(size_t)n * KN + tid];
    }
    __syncthreads();

    const int h = tid >> 5;
    const int lane = tid & 31;
    const int hofs = h * DD + lane;

    const float qv = qkv[(size_t)n * 768 + hofs];

    float sc[KN];
#pragma unroll
    for (int k = 0; k < KN; k++) {
        float p = qv * qkv[(size_t)s_m[k] * 768 + 256 + hofs];
        p += __shfl_xor_sync(0xffffffffu, p, 16);
        p += __shfl_xor_sync(0xffffffffu, p, 8);
        p += __shfl_xor_sync(0xffffffffu, p, 4);
        p += __shfl_xor_sync(0xffffffffu, p, 2);
        p += __shfl_xor_sync(0xffffffffu, p, 1);
        sc[k] = p;
    }

    const float NEGINF = __int_as_float(0xff800000);
    float mx = NEGINF;
#pragma unroll
    for (int k = 0; k < KN; k++) {
        sc[k] = s_mask[k] ? NEGINF : sc[k] * 0.1767766952966369f; // 1/sqrt(32)
        mx = fmaxf(mx, sc[k]);
    }
    float sum = 0.0f;
#pragma unroll
    for (int k = 0; k < KN; k++) {
        sc[k] = __expf(sc[k] - mx);
        sum += sc[k];
    }
    const float inv = 1.0f / sum;

    float accv = 0.0f;
#pragma unroll
    for (int k = 0; k < KN; k++)
        accv = fmaf(sc[k], qkv[(size_t)s_m[k] * 768 + 512 + hofs], accv);

    o[(size_t)n * EE + hofs] = accv * inv;
}

// ---------------------------------------------------------------------------
// LayerNorm over E=256, warp per row (8 elems/lane), in-place.
// ---------------------------------------------------------------------------
__global__ void __launch_bounds__(256)
ln_kernel(float* __restrict__ X, const float* __restrict__ gamma,
          const float* __restrict__ beta, int rows)
{
    const int row = blockIdx.x * 8 + (threadIdx.x >> 5);
    if (row >= rows) return;
    const int lane = threadIdx.x & 31;
    float* xr = X + (size_t)row * EE;

    float v[8];
    float s = 0.0f;
#pragma unroll
    for (int i = 0; i < 8; i++) {
        v[i] = xr[lane + i * 32];
        s += v[i];
    }
#pragma unroll
    for (int d = 16; d > 0; d >>= 1) s += __shfl_xor_sync(0xffffffffu, s, d);
    const float mean = s * (1.0f / 256.0f);

    float var = 0.0f;
#pragma unroll
    for (int i = 0; i < 8; i++) {
        const float d = v[i] - mean;
        var = fmaf(d, d, var);
    }
#pragma unroll
    for (int d = 16; d > 0; d >>= 1) var += __shfl_xor_sync(0xffffffffu, var, d);
    const float rstd = rsqrtf(var * (1.0f / 256.0f) + 1e-5f);

#pragma unroll
    for (int i = 0; i < 8; i++) {
        const int c = lane + i * 32;
        xr[c] = (v[i] - mean) * rstd * gamma[c] + beta[c];
    }
}

// ---------------------------------------------------------------------------
extern "C" void kernel_launch(void* const* d_in, const int* in_sizes, int n_in,
                              void* d_out, int out_size)
{
    const float* mq    = (const float*)d_in[0];
    const float* Wq    = (const float*)d_in[1];
    const float* bq    = (const float*)d_in[2];
    const float* Wk    = (const float*)d_in[3];
    const float* bk    = (const float*)d_in[4];
    const float* Wv    = (const float*)d_in[5];
    const float* bv    = (const float*)d_in[6];
    const float* Wo    = (const float*)d_in[7];
    const float* bo    = (const float*)d_in[8];
    const float* ln1g  = (const float*)d_in[9];
    const float* ln1b  = (const float*)d_in[10];
    const float* W1    = (const float*)d_in[11];
    const float* b1    = (const float*)d_in[12];
    const float* W2    = (const float*)d_in[13];
    const float* b2    = (const float*)d_in[14];
    const float* ln2g  = (const float*)d_in[15];
    const float* ln2b  = (const float*)d_in[16];
    const void*  bidx  = d_in[17];
    const void*  graph = d_in[18];
    const void*  mask  = d_in[19];

    float* out = (float*)d_out;

    float* qkv; cudaGetSymbolAddress((void**)&qkv, g_qkv);
    float* o;   cudaGetSymbolAddress((void**)&o,   g_o);
    float* x;   cudaGetSymbolAddress((void**)&x,   g_x);
    float* hbuf;cudaGetSymbolAddress((void**)&hbuf,g_h);

    const int M = NTOK;
    const int MB = (M + 127) / 128;   // 431

    // 0) Detect index/mask dtypes and canonicalize
    detect_kernel<<<1, 256>>>(bidx, mask);
    convert_kernel<<<256, 256>>>(bidx, graph, mask);

    // 1) Q/K/V projections of ALL vertices (project-then-gather)
    {
        dim3 grid(MB, 2);
        gemm_kernel<false, false><<<grid, 256>>>(mq, Wq, bq, qkv + 0,   nullptr, M, EE, 768);
        gemm_kernel<false, false><<<grid, 256>>>(mq, Wk, bk, qkv + 256, nullptr, M, EE, 768);
        gemm_kernel<false, false><<<grid, 256>>>(mq, Wv, bv, qkv + 512, nullptr, M, EE, 768);
    }

    // 2) Attention with gathered K/V rows
    attn_kernel<<<M, 256>>>(qkv, o);

    // 3) Wo projection + residual(mq) -> x_pre, then LN1 in-place
    {
        dim3 grid(MB, 2);
        gemm_kernel<true, false><<<grid, 256>>>(o, Wo, bo, x, mq, M, EE, EE);
        ln_kernel<<<(M + 7) / 8, 256>>>(x, ln1g, ln1b, M);
    }

    // 4) FFN1 + exact GELU
    {
        dim3 grid(MB, 8);
        gemm_kernel<false, true><<<grid, 256>>>(x, W1, b1, hbuf, nullptr, M, EE, FF);
    }

    // 5) FFN2 + residual(x) -> out, then LN2 in-place
    {
        dim3 grid(MB, 2);
        gemm_kernel<true, false><<<grid, 256>>>(hbuf, W2, b2, out, x, M, FF, EE);
        ln_kernel<<<(M + 7) / 8, 256>>>(out, ln2g, ln2b, M);
    }
}